// round 1
// baseline (speedup 1.0000x reference)
#include <cuda_runtime.h>
#include <cstdint>

// Hand_Input_Sorter: per-frame conditional half-swap.
// X: [B*S, 130] fp32. skip predicate from elements 0 (h0), 1 (p0), 65 (h1), 66 (p1).
// out = skip ? X : X with 65-element halves swapped.

static constexpr int FRAME_LEN = 130;
static constexpr int HALF = 65;

__global__ __launch_bounds__(256) void hand_sorter_kernel(
    const float* __restrict__ X,
    float* __restrict__ out,
    int n_frames)
{
    const int warps_per_block = blockDim.x >> 5;
    const int gwarp = blockIdx.x * warps_per_block + (threadIdx.x >> 5);
    if (gwarp >= n_frames) return;
    const int lane = threadIdx.x & 31;

    const float* __restrict__ f = X + (size_t)gwarp * FRAME_LEN;
    float* __restrict__ o = out + (size_t)gwarp * FRAME_LEN;

    // Front-batched loads: lane covers j = lane, lane+32, lane+64, lane+96, lane+128.
    // v4 only valid for lanes 0,1 (j=128,129).
    float v0 = f[lane];
    float v1 = f[lane + 32];
    float v2 = f[lane + 64];
    float v3 = f[lane + 96];
    float v4 = 0.0f;
    if (lane < FRAME_LEN - 128) v4 = f[lane + 128];

    // Extract predicate inputs via shuffle (no extra global loads):
    //   h0 = X[0]  -> v0 lane 0
    //   p0 = X[1]  -> v0 lane 1
    //   h1 = X[65] -> v2 lane 1  (65 = 64 + 1)
    //   p1 = X[66] -> v2 lane 2
    const unsigned FULL = 0xFFFFFFFFu;
    float h0 = __shfl_sync(FULL, v0, 0);
    float p0 = __shfl_sync(FULL, v0, 1);
    float h1 = __shfl_sync(FULL, v2, 1);
    float p1 = __shfl_sync(FULL, v2, 2);

    bool nan0 = isnan(h0);
    bool nan1 = isnan(h1);

    // skip1: h1 > h0 (false if either NaN — IEEE semantics match jnp)
    bool skip = (h1 > h0);
    // skip2: both NaN
    skip |= (nan0 && nan1);
    // skip3: only hand1 present, labeled right (h1 == 1)
    skip |= (nan0 && (h1 == 1.0f));
    // skip4: only hand0 present, labeled left (h0 == 0)
    skip |= (nan1 && (h0 == 0.0f));
    // skip5/skip6: both present, equal labels, prob ordering
    if (!nan0 && !nan1 && (h0 == h1)) {
        skip |= ((h0 == 0.0f) && (p0 > p1));
        skip |= ((h0 == 1.0f) && (p0 < p1));
    }

    // Store: identity if skip, else half-swap destination.
    // All lanes in the warp share `skip`, so stores stay coalesced.
    #pragma unroll
    for (int i = 0; i < 5; i++) {
        int j = lane + 32 * i;
        if (j >= FRAME_LEN) break;
        float v;
        switch (i) {
            case 0: v = v0; break;
            case 1: v = v1; break;
            case 2: v = v2; break;
            case 3: v = v3; break;
            default: v = v4; break;
        }
        int dst = skip ? j : (j < HALF ? j + HALF : j - HALF);
        o[dst] = v;
    }
}

extern "C" void kernel_launch(void* const* d_in, const int* in_sizes, int n_in,
                              void* d_out, int out_size)
{
    const float* X = (const float*)d_in[0];
    // d_in[1] is the swap_pattern (int32[130]); it is the fixed 65<->65 half swap,
    // computed analytically in-kernel, so it is not gathered.
    float* out = (float*)d_out;

    int n_frames = in_sizes[0] / FRAME_LEN;

    const int threads = 256;
    const int warps_per_block = threads / 32;
    int blocks = (n_frames + warps_per_block - 1) / warps_per_block;

    hand_sorter_kernel<<<blocks, threads>>>(X, out, n_frames);
}